// round 16
// baseline (speedup 1.0000x reference)
#include <cuda_runtime.h>
#include <cuda_fp16.h>
#include <math.h>

typedef unsigned long long ull;

// ---- problem constants ----
#define BB  16
#define HH  384
#define WW  512
#define HPP 191
#define WPP 255
#define H2D 189
#define W2D 253
#define H3D 187
#define W3D 251
#define NPIX (H3D*W3D)   // 46937
#define NEGV (-1e30f)
#define THRESH_V 0.6f
#define KPICKS 128
#define CAP 5600
#define SP  260          // padded row stride (mult of 4)
#define PH  196          // padded plane height

// logit(0.6) = ln(1.5); fp16-filter band 0.12 >> fp16 conv error (~0.02 @5sigma)
#define LOGIT06 0.40546510810816444f
#define BANDF   0.12f

// staging layout offsets (in ull) — ALL EVEN for aligned 16B loads
#define W1OFF 0
#define W1N   135
#define W2OFF 136
#define W2N   720
#define W3OFF 856
#define W3N   2304
#define W3HOFF 3160       // fp16 oc-pair conv3 weights: 2304 half2 = 1152 ull
#define W3HN_ULL 1152
#define WTOT  4312

// ---- scratch (zero-initialized device globals; padding deterministic) ----
__device__ __align__(16) float  g_pool[BB*10*PH*SP];
__device__ __align__(16) float  g_h2[BB*16*PH*SP];
__device__ __align__(16) __half g_h2h[BB*16*PH*SP];
__device__ __align__(16) ull    g_stage[WTOT];
__device__ int    g_cnt[BB];
__device__ int    g_wcnt;
__device__ int    g_work[BB*NPIX];      // packed (bb<<20)|(y<<10)|x
__device__ int    g_cand[BB*NPIX];      // packed (y<<16)|x
__device__ float  g_cand_sc[BB*NPIX];

// ---- all packed weights in ONE constant bank (one memcpy) ----
__constant__ ull c_wall[WTOT];

// ---- helpers ----
__device__ __forceinline__ ull pack2(float lo, float hi){
    ull r; asm("mov.b64 %0, {%1, %2};" : "=l"(r) : "f"(lo), "f"(hi)); return r;
}
__device__ __forceinline__ void unpack2(ull v, float &lo, float &hi){
    asm("mov.b64 {%0, %1}, %2;" : "=f"(lo), "=f"(hi) : "l"(v));
}
__device__ __forceinline__ void fma2(ull &d, ull a, ull b){
    asm("fma.rn.f32x2 %0, %1, %2, %0;" : "+l"(d) : "l"(a), "l"(b));
}
__device__ __forceinline__ __half2 u2h2(unsigned u){
    return *reinterpret_cast<__half2*>(&u);
}
__device__ __forceinline__ unsigned h22u(__half2 h){
    return *reinterpret_cast<unsigned*>(&h);
}

// ============================================================
// K0: pack weights (fp32 oc-pair + fp16 oc-pair) + zero counters
// ============================================================
__global__ void k0_pack(const float* __restrict__ w1,
                        const float* __restrict__ w2,
                        const float* __restrict__ w3)
{
    int tid = threadIdx.x;
    if (tid < BB) g_cnt[tid] = 0;
    if (tid == 0) g_wcnt = 0;
    for (int i = tid; i < W1N; i += 256){
        int ck = i / 5, q = i % 5;
        g_stage[W1OFF + i] = pack2(w1[(2*q)*27 + ck], w1[(2*q+1)*27 + ck]);
    }
    for (int i = tid; i < W2N; i += 256){
        int ck = i >> 3, q = i & 7;
        g_stage[W2OFF + i] = pack2(w2[(2*q)*90 + ck], w2[(2*q+1)*90 + ck]);
    }
    for (int i = tid; i < W3N; i += 256){
        int ck = i >> 4, q = i & 15;
        g_stage[W3OFF + i] = pack2(w3[(2*q)*144 + ck], w3[(2*q+1)*144 + ck]);
    }
    // fp16 oc-pair weights for the filter: [(c*9+k)*16 + q] as half2
    __half2* hw = reinterpret_cast<__half2*>(&g_stage[W3HOFF]);
    for (int i = tid; i < 2304; i += 256){
        int ck = i >> 4, q = i & 15;
        hw[i] = __floats2half2_rn(w3[(2*q)*144 + ck], w3[(2*q+1)*144 + ck]);
    }
}

// ============================================================
// K1: normalize + conv1(3x3,3->10) + PReLU + maxpool2x2
// ============================================================
__global__ __launch_bounds__(256) void k1_conv1_pool(const float* __restrict__ im,
                              const float* __restrict__ b,
                              const float* __restrict__ p)
{
    __shared__ float sb[10], sp[10];
    int tid = threadIdx.y * 32 + threadIdx.x;
    if (tid < 10){ sb[tid] = b[tid]; sp[tid] = p[tid]; }
    __syncthreads();

    int ox = blockIdx.x * 32 + threadIdx.x;
    int oy = blockIdx.y * 8  + threadIdx.y;
    int bb = blockIdx.z;
    if (ox >= WPP || oy >= HPP) return;

    ull acc[4][5];
#pragma unroll
    for (int q = 0; q < 5; q++){
        ull bi = pack2(sb[2*q], sb[2*q+1]);
        acc[0][q] = bi; acc[1][q] = bi; acc[2][q] = bi; acc[3][q] = bi;
    }

#pragma unroll
    for (int c = 0; c < 3; c++){
        const float* base = im + ((bb*3 + c)*HH + 2*oy)*WW + 2*ox;
        ull du[4][4];
#pragma unroll
        for (int r = 0; r < 4; r++){
            float2 u01 = *reinterpret_cast<const float2*>(base + r*WW);
            float2 u23 = *reinterpret_cast<const float2*>(base + r*WW + 2);
            float v0 = (u01.x - 127.5f)*0.0078125f;
            float v1 = (u01.y - 127.5f)*0.0078125f;
            float v2 = (u23.x - 127.5f)*0.0078125f;
            float v3 = (u23.y - 127.5f)*0.0078125f;
            du[r][0] = pack2(v0,v0); du[r][1] = pack2(v1,v1);
            du[r][2] = pack2(v2,v2); du[r][3] = pack2(v3,v3);
        }
#pragma unroll
        for (int ky = 0; ky < 3; ky++)
#pragma unroll
        for (int kx = 0; kx < 3; kx++){
            const ull* wq = &c_wall[W1OFF + (c*9 + ky*3 + kx)*5];
#pragma unroll
            for (int q = 0; q < 5; q++){
                ull wv = wq[q];
                fma2(acc[0][q], du[ky  ][kx  ], wv);
                fma2(acc[1][q], du[ky  ][kx+1], wv);
                fma2(acc[2][q], du[ky+1][kx  ], wv);
                fma2(acc[3][q], du[ky+1][kx+1], wv);
            }
        }
    }
#pragma unroll
    for (int q = 0; q < 5; q++){
        float h[4][2];
#pragma unroll
        for (int pp = 0; pp < 4; pp++) unpack2(acc[pp][q], h[pp][0], h[pp][1]);
#pragma unroll
        for (int s = 0; s < 2; s++){
            int oc = 2*q + s;
            float al = sp[oc];
            float m = -INFINITY;
#pragma unroll
            for (int pp = 0; pp < 4; pp++){
                float v = h[pp][s];
                v = v > 0.f ? v : al*v;
                m = fmaxf(m, v);
            }
            g_pool[((bb*10 + oc)*PH + oy)*SP + ox] = m;
        }
    }
}

// ============================================================
// K2: conv2(3x3,10->16) + PReLU, 4 px/thread.
// Writes fp32 h2 (exact path) AND fp16 h2 (filter path).
// ============================================================
__global__ __launch_bounds__(128) void k2_conv2(const float* __restrict__ b,
                         const float* __restrict__ p)
{
    __shared__ float sb[16], sp[16];
    int tid = threadIdx.y * 32 + threadIdx.x;
    if (tid < 16){ sb[tid] = b[tid]; sp[tid] = p[tid]; }
    __syncthreads();

    int x0 = blockIdx.x * 128 + threadIdx.x * 4;  // <= 252; reads <= 257 < SP
    int oy = blockIdx.y * 4   + threadIdx.y;
    int bb = blockIdx.z;
    if (oy >= H2D) return;

    ull acc[4][8];
#pragma unroll
    for (int q = 0; q < 8; q++){
        ull bi = pack2(sb[2*q], sb[2*q+1]);
        acc[0][q] = bi; acc[1][q] = bi; acc[2][q] = bi; acc[3][q] = bi;
    }

    for (int c = 0; c < 10; c++){
        const float* base = g_pool + ((bb*10 + c)*PH + oy)*SP + x0;
        ull du[3][6];
#pragma unroll
        for (int r = 0; r < 3; r++){
            float4 a4 = *reinterpret_cast<const float4*>(base + r*SP);
            float2 b2 = *reinterpret_cast<const float2*>(base + r*SP + 4);
            du[r][0] = pack2(a4.x,a4.x); du[r][1] = pack2(a4.y,a4.y);
            du[r][2] = pack2(a4.z,a4.z); du[r][3] = pack2(a4.w,a4.w);
            du[r][4] = pack2(b2.x,b2.x); du[r][5] = pack2(b2.y,b2.y);
        }
#pragma unroll
        for (int ky = 0; ky < 3; ky++)
#pragma unroll
        for (int kx = 0; kx < 3; kx++){
            const ull* wq = &c_wall[W2OFF + (c*9 + ky*3 + kx)*8];
#pragma unroll
            for (int q = 0; q < 8; q++){
                ull wv = wq[q];
#pragma unroll
                for (int pp = 0; pp < 4; pp++)
                    fma2(acc[pp][q], du[ky][kx+pp], wv);
            }
        }
    }
#pragma unroll
    for (int q = 0; q < 8; q++){
        float v[4][2];
#pragma unroll
        for (int pp = 0; pp < 4; pp++) unpack2(acc[pp][q], v[pp][0], v[pp][1]);
#pragma unroll
        for (int s = 0; s < 2; s++){
            int oc = 2*q + s;
            float al = sp[oc];
            float4 o;
            float t0 = v[0][s]; o.x = t0 > 0.f ? t0 : al*t0;
            float t1 = v[1][s]; o.y = t1 > 0.f ? t1 : al*t1;
            float t2 = v[2][s]; o.z = t2 > 0.f ? t2 : al*t2;
            float t3 = v[3][s]; o.w = t3 > 0.f ? t3 : al*t3;
            size_t idx = ((size_t)(bb*16 + oc)*PH + oy)*SP + x0;
            *reinterpret_cast<float4*>(&g_h2[idx]) = o;
            uint2 hs;
            hs.x = h22u(__floats2half2_rn(o.x, o.y));
            hs.y = h22u(__floats2half2_rn(o.z, o.w));
            *reinterpret_cast<uint2*>(&g_h2h[idx]) = hs;
        }
    }
}

// ============================================================
// K3F: fp16 HFMA2 conv3 FILTER (decision-only). Identical shape
// to the proven fp32 engine (4 px/thread, 16 oc-pairs, 128 thr)
// but half2 accumulators at rt=2 instead of f32x2 at rt=3.
// Appends pixels with approx logit > logit(0.6)-BANDF to worklist.
// ============================================================
__global__ __launch_bounds__(128) void k3_filter(const float* __restrict__ b3,
                               const float* __restrict__ p3,
                               const float* __restrict__ w41, const float* __restrict__ b41)
{
    __shared__ float sp[32], sw41[64], sb41[2];
    __shared__ unsigned sbh[16];   // bias as half2 oc-pairs
    int tid = threadIdx.y * 32 + threadIdx.x;
    if (tid < 32) sp[tid] = p3[tid];
    if (tid < 64) sw41[tid] = w41[tid];
    if (tid < 2)  sb41[tid] = b41[tid];
    if (tid < 16) sbh[tid] = h22u(__floats2half2_rn(b3[2*tid], b3[2*tid+1]));
    __syncthreads();

    int x0 = blockIdx.x * 128 + threadIdx.x * 4;  // <= 252; reads halfs <= 257 < SP
    int oy = blockIdx.y * 4   + threadIdx.y;
    int bb = blockIdx.z;
    if (oy >= H3D) return;

    __half2 acc[4][16];
#pragma unroll
    for (int q = 0; q < 16; q++){
        __half2 bi = u2h2(sbh[q]);
        acc[0][q] = bi; acc[1][q] = bi; acc[2][q] = bi; acc[3][q] = bi;
    }

    const uint4* wbase = reinterpret_cast<const uint4*>(
        reinterpret_cast<const char*>(c_wall) + (size_t)W3HOFF*8);

    for (int c = 0; c < 16; c++){
        const __half* base = g_h2h + ((size_t)(bb*16 + c)*PH + oy)*SP + x0;
        __half2 du[3][6];
#pragma unroll
        for (int r = 0; r < 3; r++){
            const unsigned* bp = reinterpret_cast<const unsigned*>(base + r*SP);
            uint2 ua = *reinterpret_cast<const uint2*>(bp);
            unsigned ub = bp[2];
            __half2 p01 = u2h2(ua.x), p23 = u2h2(ua.y), p45 = u2h2(ub);
            du[r][0] = __half2half2(__low2half(p01));
            du[r][1] = __half2half2(__high2half(p01));
            du[r][2] = __half2half2(__low2half(p23));
            du[r][3] = __half2half2(__high2half(p23));
            du[r][4] = __half2half2(__low2half(p45));
            du[r][5] = __half2half2(__high2half(p45));
        }
#pragma unroll
        for (int ky = 0; ky < 3; ky++)
#pragma unroll
        for (int kx = 0; kx < 3; kx++){
            const uint4* wq = wbase + (c*9 + ky*3 + kx)*4;
#pragma unroll
            for (int g = 0; g < 4; g++){
                uint4 w4 = wq[g];
                __half2 w0 = u2h2(w4.x), w1 = u2h2(w4.y);
                __half2 w2 = u2h2(w4.z), w3 = u2h2(w4.w);
#pragma unroll
                for (int pp = 0; pp < 4; pp++){
                    __half2 d = du[ky][kx+pp];
                    acc[pp][4*g+0] = __hfma2(d, w0, acc[pp][4*g+0]);
                    acc[pp][4*g+1] = __hfma2(d, w1, acc[pp][4*g+1]);
                    acc[pp][4*g+2] = __hfma2(d, w2, acc[pp][4*g+2]);
                    acc[pp][4*g+3] = __hfma2(d, w3, acc[pp][4*g+3]);
                }
            }
        }
    }

    // approximate score head (fp32)
    float l0[4], l1[4];
#pragma unroll
    for (int pp = 0; pp < 4; pp++){ l0[pp] = sb41[0]; l1[pp] = sb41[1]; }
#pragma unroll
    for (int q = 0; q < 16; q++){
        float wA0 = sw41[2*q],    wA1 = sw41[2*q+1];
        float wB0 = sw41[32+2*q], wB1 = sw41[32+2*q+1];
        float alo = sp[2*q], ahi = sp[2*q+1];
#pragma unroll
        for (int pp = 0; pp < 4; pp++){
            float2 f = __half22float2(acc[pp][q]);
            float hA = f.x > 0.f ? f.x : alo*f.x;
            float hB = f.y > 0.f ? f.y : ahi*f.y;
            l0[pp] = fmaf(hA, wA0, fmaf(hB, wA1, l0[pp]));
            l1[pp] = fmaf(hA, wB0, fmaf(hB, wB1, l1[pp]));
        }
    }
    const float thr = LOGIT06 - BANDF;
#pragma unroll
    for (int pp = 0; pp < 4; pp++){
        int x = x0 + pp;
        if (x < W3D && (l1[pp] - l0[pp]) > thr){
            int pos = atomicAdd(&g_wcnt, 1);
            if (pos < BB*NPIX) g_work[pos] = (bb << 20) | (oy << 10) | x;
        }
    }
}

// ============================================================
// K3X: exact conv3 + score head at worklist pixels (R5-identical
// sequential (c,ky,kx,q) FFMA2 chain -> bitwise-exact scores).
// Appends candidates for NMS.
// ============================================================
__global__ __launch_bounds__(128) void k3_exact(const float* __restrict__ b3,
                               const float* __restrict__ p3,
                               const float* __restrict__ w41, const float* __restrict__ b41)
{
    __shared__ __align__(16) ull sw3[2304];   // [(c*9+k)*16 + q]
    __shared__ float sb[32], sp[32], sw41[64], sb41[2];
    int tid = threadIdx.x;
    {
        ulonglong2* d = reinterpret_cast<ulonglong2*>(sw3);
        const ulonglong2* s = reinterpret_cast<const ulonglong2*>(&g_stage[W3OFF]);
        for (int i = tid; i < 1152; i += 128) d[i] = s[i];
    }
    if (tid < 32){ sb[tid] = b3[tid]; sp[tid] = p3[tid]; }
    if (tid < 64) sw41[tid] = w41[tid];
    if (tid < 2)  sb41[tid] = b41[tid];
    __syncthreads();

    int n = g_wcnt;
    if (n > BB*NPIX) n = BB*NPIX;

    for (int i = blockIdx.x * 128 + tid; i < n; i += gridDim.x * 128){
        int w = g_work[i];
        int x  = w & 1023;
        int y  = (w >> 10) & 1023;
        int bb = w >> 20;

        ull acc[16];
#pragma unroll
        for (int q = 0; q < 16; q++) acc[q] = pack2(sb[2*q], sb[2*q+1]);

        for (int c = 0; c < 16; c++){
            const float* base = g_h2 + ((size_t)(bb*16 + c)*PH + y)*SP + x;
#pragma unroll
            for (int ky = 0; ky < 3; ky++){
                float v0 = base[ky*SP + 0];
                float v1 = base[ky*SP + 1];
                float v2 = base[ky*SP + 2];
                ull d0 = pack2(v0,v0), d1 = pack2(v1,v1), d2 = pack2(v2,v2);
                const ull* wq = &sw3[(c*9 + ky*3)*16];
#pragma unroll
                for (int q = 0; q < 16; q++) fma2(acc[q], d0, wq[q]);
#pragma unroll
                for (int q = 0; q < 16; q++) fma2(acc[q], d1, wq[16+q]);
#pragma unroll
                for (int q = 0; q < 16; q++) fma2(acc[q], d2, wq[32+q]);
            }
        }

        float l0 = sb41[0], l1 = sb41[1];
#pragma unroll
        for (int q = 0; q < 16; q++){
            float hA, hB; unpack2(acc[q], hA, hB);
            float alo = sp[2*q], ahi = sp[2*q+1];
            hA = hA > 0.f ? hA : alo*hA;
            hB = hB > 0.f ? hB : ahi*hB;
            float wA0 = sw41[2*q],    wA1 = sw41[2*q+1];
            float wB0 = sw41[32+2*q], wB1 = sw41[32+2*q+1];
            l0 = fmaf(hA, wA0, fmaf(hB, wA1, l0));
            l1 = fmaf(hA, wB0, fmaf(hB, wB1, l1));
        }
        float prob = 1.f / (1.f + expf(l0 - l1));
        if (prob >= THRESH_V){
            int pos = atomicAdd(&g_cnt[bb], 1);
            if (pos < NPIX){
                g_cand[bb*NPIX + pos]    = (y << 16) | x;
                g_cand_sc[bb*NPIX + pos] = prob;
            }
        }
    }
}

// ============================================================
// K4: per-batch iterative argmax NMS (1 barrier/pick) + fused
// pick finishing (exact reg head + box math, R5-identical chain).
// Tie-break (score desc, xy asc) == pixel-index order.
// IoU>0.5 <=> |dx|<=1 && |dy|<=1.
// ============================================================
__global__ __launch_bounds__(256) void k4_nms(const float* __restrict__ b3,
                                              const float* __restrict__ p3,
                                              const float* __restrict__ w42,
                                              const float* __restrict__ b42,
                                              float* __restrict__ out)
{
    const int NT = 256;
    int bb = blockIdx.x, tid = threadIdx.x;
    int lane = tid & 31, wrp = tid >> 5;

    __shared__ __align__(16) char s_buf[CAP*8];   // candidates, then weights
    __shared__ float w_s[2][8];
    __shared__ int   w_xy[2][8];
    __shared__ int   s_pick[KPICKS];
    __shared__ float s_psc[KPICKS];
    __shared__ int   s_pcnt;
    __shared__ float sb[32], sp[32], sw42[128], sb42[4];

    float* s_sc = reinterpret_cast<float*>(s_buf);
    int*   s_xy = reinterpret_cast<int*>(s_buf + CAP*4);

    if (tid == 0) s_pcnt = KPICKS;

    int count = g_cnt[bb];
    if (count > NPIX) count = NPIX;
    bool insh = (count <= CAP);
    float* scp;
    const int* xyp;
    if (insh){
        for (int i = tid; i < count; i += NT){
            s_sc[i] = g_cand_sc[bb*NPIX + i];
            s_xy[i] = g_cand[bb*NPIX + i];
        }
        scp = s_sc; xyp = s_xy;
    } else {
        scp = g_cand_sc + bb*NPIX;
        xyp = g_cand + bb*NPIX;
    }
    __syncthreads();

    int prev_jx = -1000, prev_jy = -1000;   // uniform across threads
    for (int k = 0; k < KPICKS; k++){
        int buf = k & 1;
        float bs = -INFINITY; int bxy = 0x7fffffff;
        for (int i = tid; i < count; i += NT){
            float v = scp[i]; int xy = xyp[i];
            int dx = (xy & 0xffff) - prev_jx; dx = dx < 0 ? -dx : dx;
            int dy = (xy >> 16)    - prev_jy; dy = dy < 0 ? -dy : dy;
            if (dx <= 1 && dy <= 1){ v = NEGV; scp[i] = NEGV; }
            if (v > bs || (v == bs && xy < bxy)){ bs = v; bxy = xy; }
        }
#pragma unroll
        for (int off = 16; off > 0; off >>= 1){
            float vs  = __shfl_down_sync(0xffffffffu, bs,  off);
            int   vxy = __shfl_down_sync(0xffffffffu, bxy, off);
            if (vs > bs || (vs == bs && vxy < bxy)){ bs = vs; bxy = vxy; }
        }
        if (lane == 0){ w_s[buf][wrp] = bs; w_xy[buf][wrp] = bxy; }
        __syncthreads();
        float best = w_s[buf][0]; int jxy = w_xy[buf][0];
#pragma unroll
        for (int t = 1; t < 8; t++){
            float v = w_s[buf][t]; int xy = w_xy[buf][t];
            if (v > best || (v == best && xy < jxy)){ best = v; jxy = xy; }
        }

        if (!(best > -0.5e30f)){
            if (tid == 0) s_pcnt = k;
            int n0 = (KPICKS - k) * 5;
            float* o0 = out + ((size_t)bb*KPICKS + k)*5;
            for (int t = tid; t < n0; t += NT) o0[t] = 0.f;
            break;
        }

        prev_jx = jxy & 0xffff;
        prev_jy = jxy >> 16;
        if (tid == 0){ s_pick[k] = jxy; s_psc[k] = best; }
    }

    // ---- epilogue: finish the <=128 picks (candidate buffer is dead) ----
    __syncthreads();
    ull* sw3 = reinterpret_cast<ull*>(s_buf);     // 18432 B <= 44800 B
    {
        ulonglong2* d = reinterpret_cast<ulonglong2*>(sw3);
        const ulonglong2* s = reinterpret_cast<const ulonglong2*>(&g_stage[W3OFF]);
        for (int i = tid; i < 1152; i += NT) d[i] = s[i];
    }
    if (tid < 32){ sb[tid] = b3[tid]; sp[tid] = p3[tid]; }
    if (tid < 128) sw42[tid] = w42[tid];
    if (tid < 4)   sb42[tid] = b42[tid];
    __syncthreads();

    int pcnt = s_pcnt;
    if (tid < pcnt){
        int jxy = s_pick[tid];
        int x = jxy & 0xffff;
        int y = jxy >> 16;

        ull acc[16];
#pragma unroll
        for (int q = 0; q < 16; q++) acc[q] = pack2(sb[2*q], sb[2*q+1]);

        for (int c = 0; c < 16; c++){
            const float* base = g_h2 + ((size_t)(bb*16 + c)*PH + y)*SP + x;
#pragma unroll
            for (int ky = 0; ky < 3; ky++){
                float v0 = base[ky*SP + 0];
                float v1 = base[ky*SP + 1];
                float v2 = base[ky*SP + 2];
                ull d0 = pack2(v0,v0), d1 = pack2(v1,v1), d2 = pack2(v2,v2);
                const ull* wq = &sw3[(c*9 + ky*3)*16];
#pragma unroll
                for (int q = 0; q < 16; q++) fma2(acc[q], d0, wq[q]);
#pragma unroll
                for (int q = 0; q < 16; q++) fma2(acc[q], d1, wq[16+q]);
#pragma unroll
                for (int q = 0; q < 16; q++) fma2(acc[q], d2, wq[32+q]);
            }
        }

        float r0 = sb42[0], r1 = sb42[1], r2 = sb42[2], r3 = sb42[3];
#pragma unroll
        for (int q = 0; q < 16; q++){
            float hA, hB; unpack2(acc[q], hA, hB);
            float alo = sp[2*q], ahi = sp[2*q+1];
            hA = hA > 0.f ? hA : alo*hA;
            hB = hB > 0.f ? hB : ahi*hB;
            float q00 = sw42[2*q],    q01 = sw42[2*q+1];
            float q10 = sw42[32+2*q], q11 = sw42[32+2*q+1];
            float q20 = sw42[64+2*q], q21 = sw42[64+2*q+1];
            float q30 = sw42[96+2*q], q31 = sw42[96+2*q+1];
            r0 = fmaf(hA, q00, fmaf(hB, q01, r0));
            r1 = fmaf(hA, q10, fmaf(hB, q11, r1));
            r2 = fmaf(hA, q20, fmaf(hB, q21, r2));
            r3 = fmaf(hA, q30, fmaf(hB, q31, r3));
        }

        float x1 = 2.f*x + 1.f,  y1 = 2.f*y + 1.f;
        float x2 = 2.f*x + 12.f, y2 = 2.f*y + 12.f;
        float q1 = fmaf(r0, 11.f, x1);
        float q2 = fmaf(r1, 11.f, y1);
        float q3 = fmaf(r2, 11.f, x2);
        float q4 = fmaf(r3, 11.f, y2);
        float rw = q3 - q1, rh = q4 - q2;
        float l = fmaxf(rw, rh);
        float nx1 = q1 + rw*0.5f - l*0.5f;
        float ny1 = q2 + rh*0.5f - l*0.5f;
        float* o = out + ((size_t)bb*KPICKS + tid)*5;
        o[0] = nx1; o[1] = ny1; o[2] = nx1 + l; o[3] = ny1 + l;
        o[4] = s_psc[tid];
    }
}

// ============================================================
extern "C" void kernel_launch(void* const* d_in, const int* in_sizes, int n_in,
                              void* d_out, int out_size)
{
    const float* im   = (const float*)d_in[0];
    const float* c1w  = (const float*)d_in[1];
    const float* c1b  = (const float*)d_in[2];
    const float* p1   = (const float*)d_in[3];
    const float* c2w  = (const float*)d_in[4];
    const float* c2b  = (const float*)d_in[5];
    const float* p2   = (const float*)d_in[6];
    const float* c3w  = (const float*)d_in[7];
    const float* c3b  = (const float*)d_in[8];
    const float* p3   = (const float*)d_in[9];
    const float* c41w = (const float*)d_in[10];
    const float* c41b = (const float*)d_in[11];
    const float* c42w = (const float*)d_in[12];
    const float* c42b = (const float*)d_in[13];
    float* out = (float*)d_out;

    // stage packed weights; ONE copy into the single constant bank
    k0_pack<<<1, 256>>>(c1w, c2w, c3w);
    void* stage_ptr = nullptr;
    cudaGetSymbolAddress(&stage_ptr, g_stage);
    cudaMemcpyToSymbolAsync(c_wall, stage_ptr, (size_t)WTOT*8, 0,
                            cudaMemcpyDeviceToDevice, 0);

    dim3 blk1(32, 8, 1);
    dim3 g1(8, 24, BB);

    dim3 blk2(32, 4, 1);
    dim3 g2(2, 48, BB);   // 48*4 rows cover 189 (pad rows early-out)
    dim3 g3(2, 47, BB);   // 47*4 rows cover 187 (pad row early-out)

    k1_conv1_pool<<<g1, blk1>>>(im, c1b, p1);
    k2_conv2<<<g2, blk2>>>(c2b, p2);
    k3_filter<<<g3, blk2>>>(c3b, p3, c41w, c41b);
    k3_exact<<<592, 128>>>(c3b, p3, c41w, c41b);
    k4_nms<<<BB, 256>>>(c3b, p3, c42w, c42b, out);
}

// round 17
// speedup vs baseline: 1.0751x; 1.0751x over previous
#include <cuda_runtime.h>
#include <math.h>

typedef unsigned long long ull;

// ---- problem constants ----
#define BB  16
#define HH  384
#define WW  512
#define HPP 191
#define WPP 255
#define H2D 189
#define W2D 253
#define H3D 187
#define W3D 251
#define NPIX (H3D*W3D)   // 46937
#define NEGV (-1e30f)
#define THRESH_V 0.6f
#define KPICKS 128
#define CAP 5600
#define SP  260          // padded row stride (mult of 4)
#define PH  196          // padded plane height

// staging layout offsets (in ull) — ALL EVEN for aligned ulonglong2 loads
#define W1OFF 0
#define W1N   135
#define W2OFF 136
#define W2N   720
#define W3OFF 856
#define W3N   2304
#define WTOT  3160

// ---- scratch (zero-initialized device globals; padding deterministic) ----
__device__ __align__(16) float  g_pool[BB*10*PH*SP];
__device__ __align__(16) float  g_h2[BB*16*PH*SP];
__device__ __align__(16) ull    g_stage[WTOT];
__device__ int    g_cnt[BB];
__device__ int    g_cand[BB*NPIX];      // packed (y<<16)|x
__device__ float  g_cand_sc[BB*NPIX];

// ---- all packed oc-pair weights in ONE constant bank (one memcpy) ----
__constant__ ull c_wall[WTOT];

// ---- f32x2 helpers ----
__device__ __forceinline__ ull pack2(float lo, float hi){
    ull r; asm("mov.b64 %0, {%1, %2};" : "=l"(r) : "f"(lo), "f"(hi)); return r;
}
__device__ __forceinline__ void unpack2(ull v, float &lo, float &hi){
    asm("mov.b64 {%0, %1}, %2;" : "=f"(lo), "=f"(hi) : "l"(v));
}
__device__ __forceinline__ void fma2(ull &d, ull a, ull b){
    asm("fma.rn.f32x2 %0, %1, %2, %0;" : "+l"(d) : "l"(a), "l"(b));
}

// ============================================================
// K0: pack weights into oc-pair layout + zero counters
// ============================================================
__global__ void k0_pack(const float* __restrict__ w1,
                        const float* __restrict__ w2,
                        const float* __restrict__ w3)
{
    int tid = threadIdx.x;
    if (tid < BB) g_cnt[tid] = 0;
    for (int i = tid; i < W1N; i += 256){
        int ck = i / 5, q = i % 5;
        g_stage[W1OFF + i] = pack2(w1[(2*q)*27 + ck], w1[(2*q+1)*27 + ck]);
    }
    for (int i = tid; i < W2N; i += 256){
        int ck = i >> 3, q = i & 7;
        g_stage[W2OFF + i] = pack2(w2[(2*q)*90 + ck], w2[(2*q+1)*90 + ck]);
    }
    for (int i = tid; i < W3N; i += 256){
        int ck = i >> 4, q = i & 15;
        g_stage[W3OFF + i] = pack2(w3[(2*q)*144 + ck], w3[(2*q+1)*144 + ck]);
    }
}

// ============================================================
// K1: normalize + conv1(3x3,3->10) + PReLU + maxpool2x2
// ============================================================
__global__ __launch_bounds__(256) void k1_conv1_pool(const float* __restrict__ im,
                              const float* __restrict__ b,
                              const float* __restrict__ p)
{
    __shared__ float sb[10], sp[10];
    int tid = threadIdx.y * 32 + threadIdx.x;
    if (tid < 10){ sb[tid] = b[tid]; sp[tid] = p[tid]; }
    __syncthreads();

    int ox = blockIdx.x * 32 + threadIdx.x;
    int oy = blockIdx.y * 8  + threadIdx.y;
    int bb = blockIdx.z;
    if (ox >= WPP || oy >= HPP) return;

    ull acc[4][5];
#pragma unroll
    for (int q = 0; q < 5; q++){
        ull bi = pack2(sb[2*q], sb[2*q+1]);
        acc[0][q] = bi; acc[1][q] = bi; acc[2][q] = bi; acc[3][q] = bi;
    }

#pragma unroll
    for (int c = 0; c < 3; c++){
        const float* base = im + ((bb*3 + c)*HH + 2*oy)*WW + 2*ox;
        ull du[4][4];
#pragma unroll
        for (int r = 0; r < 4; r++){
            float2 u01 = *reinterpret_cast<const float2*>(base + r*WW);
            float2 u23 = *reinterpret_cast<const float2*>(base + r*WW + 2);
            float v0 = (u01.x - 127.5f)*0.0078125f;
            float v1 = (u01.y - 127.5f)*0.0078125f;
            float v2 = (u23.x - 127.5f)*0.0078125f;
            float v3 = (u23.y - 127.5f)*0.0078125f;
            du[r][0] = pack2(v0,v0); du[r][1] = pack2(v1,v1);
            du[r][2] = pack2(v2,v2); du[r][3] = pack2(v3,v3);
        }
#pragma unroll
        for (int ky = 0; ky < 3; ky++)
#pragma unroll
        for (int kx = 0; kx < 3; kx++){
            const ull* wq = &c_wall[W1OFF + (c*9 + ky*3 + kx)*5];
#pragma unroll
            for (int q = 0; q < 5; q++){
                ull wv = wq[q];
                fma2(acc[0][q], du[ky  ][kx  ], wv);
                fma2(acc[1][q], du[ky  ][kx+1], wv);
                fma2(acc[2][q], du[ky+1][kx  ], wv);
                fma2(acc[3][q], du[ky+1][kx+1], wv);
            }
        }
    }
#pragma unroll
    for (int q = 0; q < 5; q++){
        float h[4][2];
#pragma unroll
        for (int pp = 0; pp < 4; pp++) unpack2(acc[pp][q], h[pp][0], h[pp][1]);
#pragma unroll
        for (int s = 0; s < 2; s++){
            int oc = 2*q + s;
            float al = sp[oc];
            float m = -INFINITY;
#pragma unroll
            for (int pp = 0; pp < 4; pp++){
                float v = h[pp][s];
                v = v > 0.f ? v : al*v;
                m = fmaxf(m, v);
            }
            g_pool[((bb*10 + oc)*PH + oy)*SP + ox] = m;
        }
    }
}

// ============================================================
// K2: conv2(3x3,10->16) + PReLU, 4 px/thread
// pad rows (oy >= H2D) skipped: never read by kept results
// ============================================================
__global__ __launch_bounds__(128, 3) void k2_conv2(const float* __restrict__ b,
                         const float* __restrict__ p)
{
    __shared__ float sb[16], sp[16];
    int tid = threadIdx.y * 32 + threadIdx.x;
    if (tid < 16){ sb[tid] = b[tid]; sp[tid] = p[tid]; }
    __syncthreads();

    int x0 = blockIdx.x * 128 + threadIdx.x * 4;  // <= 252; reads <= 257 < SP
    int oy = blockIdx.y * 4   + threadIdx.y;
    int bb = blockIdx.z;
    if (oy >= H2D) return;

    ull acc[4][8];
#pragma unroll
    for (int q = 0; q < 8; q++){
        ull bi = pack2(sb[2*q], sb[2*q+1]);
        acc[0][q] = bi; acc[1][q] = bi; acc[2][q] = bi; acc[3][q] = bi;
    }

    for (int c = 0; c < 10; c++){
        const float* base = g_pool + ((bb*10 + c)*PH + oy)*SP + x0;
        ull du[3][6];
#pragma unroll
        for (int r = 0; r < 3; r++){
            float4 a4 = *reinterpret_cast<const float4*>(base + r*SP);
            float2 b2 = *reinterpret_cast<const float2*>(base + r*SP + 4);
            du[r][0] = pack2(a4.x,a4.x); du[r][1] = pack2(a4.y,a4.y);
            du[r][2] = pack2(a4.z,a4.z); du[r][3] = pack2(a4.w,a4.w);
            du[r][4] = pack2(b2.x,b2.x); du[r][5] = pack2(b2.y,b2.y);
        }
#pragma unroll
        for (int ky = 0; ky < 3; ky++)
#pragma unroll
        for (int kx = 0; kx < 3; kx++){
            const ull* wq = &c_wall[W2OFF + (c*9 + ky*3 + kx)*8];
#pragma unroll
            for (int q = 0; q < 8; q++){
                ull wv = wq[q];
#pragma unroll
                for (int pp = 0; pp < 4; pp++)
                    fma2(acc[pp][q], du[ky][kx+pp], wv);
            }
        }
    }
#pragma unroll
    for (int q = 0; q < 8; q++){
        float v[4][2];
#pragma unroll
        for (int pp = 0; pp < 4; pp++) unpack2(acc[pp][q], v[pp][0], v[pp][1]);
#pragma unroll
        for (int s = 0; s < 2; s++){
            int oc = 2*q + s;
            float al = sp[oc];
            float4 o;
            float t0 = v[0][s]; o.x = t0 > 0.f ? t0 : al*t0;
            float t1 = v[1][s]; o.y = t1 > 0.f ? t1 : al*t1;
            float t2 = v[2][s]; o.z = t2 > 0.f ? t2 : al*t2;
            float t3 = v[3][s]; o.w = t3 > 0.f ? t3 : al*t3;
            *reinterpret_cast<float4*>(&g_h2[((bb*16 + oc)*PH + oy)*SP + x0]) = o;
        }
    }
}

// ============================================================
// K3: conv3(3x3,16->32)+PReLU + score head ONLY + append.
// ============================================================
__global__ __launch_bounds__(128, 3) void k3_conv3_heads(const float* __restrict__ b3,
                               const float* __restrict__ p3,
                               const float* __restrict__ w41, const float* __restrict__ b41)
{
    __shared__ float sb[32], sp[32];
    __shared__ float sw41[64], sb41[2];
    int tid = threadIdx.y * 32 + threadIdx.x;
    if (tid < 32){ sb[tid] = b3[tid]; sp[tid] = p3[tid]; }
    if (tid < 64)  sw41[tid] = w41[tid];
    if (tid < 2)   sb41[tid] = b41[tid];
    __syncthreads();

    int x0 = blockIdx.x * 128 + threadIdx.x * 4;  // <= 252; reads <= 257 < SP
    int oy = blockIdx.y * 4   + threadIdx.y;
    int bb = blockIdx.z;
    if (oy >= H3D) return;

    ull acc[4][16];
#pragma unroll
    for (int q = 0; q < 16; q++){
        ull bi = pack2(sb[2*q], sb[2*q+1]);
        acc[0][q] = bi; acc[1][q] = bi; acc[2][q] = bi; acc[3][q] = bi;
    }

    for (int c = 0; c < 16; c++){
        const float* base = g_h2 + ((bb*16 + c)*PH + oy)*SP + x0;
        ull du[3][6];
#pragma unroll
        for (int r = 0; r < 3; r++){
            float4 a4 = *reinterpret_cast<const float4*>(base + r*SP);
            float2 b2 = *reinterpret_cast<const float2*>(base + r*SP + 4);
            du[r][0] = pack2(a4.x,a4.x); du[r][1] = pack2(a4.y,a4.y);
            du[r][2] = pack2(a4.z,a4.z); du[r][3] = pack2(a4.w,a4.w);
            du[r][4] = pack2(b2.x,b2.x); du[r][5] = pack2(b2.y,b2.y);
        }
#pragma unroll
        for (int ky = 0; ky < 3; ky++)
#pragma unroll
        for (int kx = 0; kx < 3; kx++){
            const ull* wq = &c_wall[W3OFF + (c*9 + ky*3 + kx)*16];
#pragma unroll
            for (int q = 0; q < 16; q++){
                ull wv = wq[q];
#pragma unroll
                for (int pp = 0; pp < 4; pp++)
                    fma2(acc[pp][q], du[ky][kx+pp], wv);
            }
        }
    }

    // score head only (l chains identical — r-FMAs were independent)
    float l0[4], l1[4];
#pragma unroll
    for (int pp = 0; pp < 4; pp++){ l0[pp] = sb41[0]; l1[pp] = sb41[1]; }
#pragma unroll
    for (int q = 0; q < 16; q++){
        float wA0 = sw41[2*q],    wA1 = sw41[2*q+1];
        float wB0 = sw41[32+2*q], wB1 = sw41[32+2*q+1];
        float alo = sp[2*q], ahi = sp[2*q+1];
#pragma unroll
        for (int pp = 0; pp < 4; pp++){
            float hA, hB; unpack2(acc[pp][q], hA, hB);
            hA = hA > 0.f ? hA : alo*hA;
            hB = hB > 0.f ? hB : ahi*hB;
            l0[pp] = fmaf(hA, wA0, fmaf(hB, wA1, l0[pp]));
            l1[pp] = fmaf(hA, wB0, fmaf(hB, wB1, l1[pp]));
        }
    }
#pragma unroll
    for (int pp = 0; pp < 4; pp++){
        int x = x0 + pp;
        if (x >= W3D) continue;
        float prob = 1.f / (1.f + expf(l0[pp] - l1[pp]));
        if (prob >= THRESH_V){
            int pos = atomicAdd(&g_cnt[bb], 1);
            if (pos < NPIX){
                g_cand[bb*NPIX + pos]    = (oy << 16) | x;
                g_cand_sc[bb*NPIX + pos] = prob;
            }
        }
    }
}

// ============================================================
// K4: per-batch iterative argmax NMS (1 barrier/pick) + fused
// pick finishing (exact reg head + box math, R5-identical chain).
// - previous pick suppressed inline in the next scan (each thread
//   exclusively owns candidates i%256==tid -> no write hazard)
// - all threads redundantly reduce the 8 warp maxima post-barrier
// - w_s/w_xy double-buffered by pick parity
// Tie-break (score desc, xy asc) == pixel-index order.
// IoU>0.5 <=> |dx|<=1 && |dy|<=1.
// ============================================================
__global__ __launch_bounds__(256) void k4_nms(const float* __restrict__ b3,
                                              const float* __restrict__ p3,
                                              const float* __restrict__ w42,
                                              const float* __restrict__ b42,
                                              float* __restrict__ out)
{
    const int NT = 256;
    int bb = blockIdx.x, tid = threadIdx.x;
    int lane = tid & 31, wrp = tid >> 5;

    __shared__ __align__(16) char s_buf[CAP*8];   // candidates, then weights
    __shared__ float w_s[2][8];
    __shared__ int   w_xy[2][8];
    __shared__ int   s_pick[KPICKS];
    __shared__ float s_psc[KPICKS];
    __shared__ int   s_pcnt;
    __shared__ float sb[32], sp[32], sw42[128], sb42[4];

    float* s_sc = reinterpret_cast<float*>(s_buf);
    int*   s_xy = reinterpret_cast<int*>(s_buf + CAP*4);

    if (tid == 0) s_pcnt = KPICKS;

    int count = g_cnt[bb];
    if (count > NPIX) count = NPIX;
    bool insh = (count <= CAP);
    float* scp;
    const int* xyp;
    if (insh){
        for (int i = tid; i < count; i += NT){
            s_sc[i] = g_cand_sc[bb*NPIX + i];
            s_xy[i] = g_cand[bb*NPIX + i];
        }
        scp = s_sc; xyp = s_xy;
    } else {
        scp = g_cand_sc + bb*NPIX;
        xyp = g_cand + bb*NPIX;
    }
    __syncthreads();

    int prev_jx = -1000, prev_jy = -1000;   // uniform across threads
    for (int k = 0; k < KPICKS; k++){
        int buf = k & 1;
        float bs = -INFINITY; int bxy = 0x7fffffff;
        for (int i = tid; i < count; i += NT){
            float v = scp[i]; int xy = xyp[i];
            int dx = (xy & 0xffff) - prev_jx; dx = dx < 0 ? -dx : dx;
            int dy = (xy >> 16)    - prev_jy; dy = dy < 0 ? -dy : dy;
            if (dx <= 1 && dy <= 1){ v = NEGV; scp[i] = NEGV; }
            if (v > bs || (v == bs && xy < bxy)){ bs = v; bxy = xy; }
        }
#pragma unroll
        for (int off = 16; off > 0; off >>= 1){
            float vs  = __shfl_down_sync(0xffffffffu, bs,  off);
            int   vxy = __shfl_down_sync(0xffffffffu, bxy, off);
            if (vs > bs || (vs == bs && vxy < bxy)){ bs = vs; bxy = vxy; }
        }
        if (lane == 0){ w_s[buf][wrp] = bs; w_xy[buf][wrp] = bxy; }
        __syncthreads();   // the ONE barrier per pick
        float best = w_s[buf][0]; int jxy = w_xy[buf][0];
#pragma unroll
        for (int t = 1; t < 8; t++){
            float v = w_s[buf][t]; int xy = w_xy[buf][t];
            if (v > best || (v == best && xy < jxy)){ best = v; jxy = xy; }
        }

        if (!(best > -0.5e30f)){
            if (tid == 0) s_pcnt = k;
            int n0 = (KPICKS - k) * 5;
            float* o0 = out + ((size_t)bb*KPICKS + k)*5;
            for (int t = tid; t < n0; t += NT) o0[t] = 0.f;
            break;
        }

        prev_jx = jxy & 0xffff;
        prev_jy = jxy >> 16;
        if (tid == 0){ s_pick[k] = jxy; s_psc[k] = best; }
    }

    // ---- epilogue: finish the <=128 picks (candidate buffer is dead) ----
    __syncthreads();
    ull* sw3 = reinterpret_cast<ull*>(s_buf);     // 18432 B <= 44800 B
    {
        ulonglong2* d = reinterpret_cast<ulonglong2*>(sw3);
        const ulonglong2* s = reinterpret_cast<const ulonglong2*>(&g_stage[W3OFF]);
        for (int i = tid; i < 1152; i += NT) d[i] = s[i];
    }
    if (tid < 32){ sb[tid] = b3[tid]; sp[tid] = p3[tid]; }
    if (tid < 128) sw42[tid] = w42[tid];
    if (tid < 4)   sb42[tid] = b42[tid];
    __syncthreads();

    int pcnt = s_pcnt;
    if (tid < pcnt){
        int jxy = s_pick[tid];
        int x = jxy & 0xffff;
        int y = jxy >> 16;

        ull acc[16];
#pragma unroll
        for (int q = 0; q < 16; q++) acc[q] = pack2(sb[2*q], sb[2*q+1]);

        for (int c = 0; c < 16; c++){
            const float* base = g_h2 + ((size_t)(bb*16 + c)*PH + y)*SP + x;
#pragma unroll
            for (int ky = 0; ky < 3; ky++){
                float v0 = base[ky*SP + 0];
                float v1 = base[ky*SP + 1];
                float v2 = base[ky*SP + 2];
                ull d0 = pack2(v0,v0), d1 = pack2(v1,v1), d2 = pack2(v2,v2);
                const ull* wq = &sw3[(c*9 + ky*3)*16];
#pragma unroll
                for (int q = 0; q < 16; q++) fma2(acc[q], d0, wq[q]);
#pragma unroll
                for (int q = 0; q < 16; q++) fma2(acc[q], d1, wq[16+q]);
#pragma unroll
                for (int q = 0; q < 16; q++) fma2(acc[q], d2, wq[32+q]);
            }
        }

        float r0 = sb42[0], r1 = sb42[1], r2 = sb42[2], r3 = sb42[3];
#pragma unroll
        for (int q = 0; q < 16; q++){
            float hA, hB; unpack2(acc[q], hA, hB);
            float alo = sp[2*q], ahi = sp[2*q+1];
            hA = hA > 0.f ? hA : alo*hA;
            hB = hB > 0.f ? hB : ahi*hB;
            float q00 = sw42[2*q],    q01 = sw42[2*q+1];
            float q10 = sw42[32+2*q], q11 = sw42[32+2*q+1];
            float q20 = sw42[64+2*q], q21 = sw42[64+2*q+1];
            float q30 = sw42[96+2*q], q31 = sw42[96+2*q+1];
            r0 = fmaf(hA, q00, fmaf(hB, q01, r0));
            r1 = fmaf(hA, q10, fmaf(hB, q11, r1));
            r2 = fmaf(hA, q20, fmaf(hB, q21, r2));
            r3 = fmaf(hA, q30, fmaf(hB, q31, r3));
        }

        float x1 = 2.f*x + 1.f,  y1 = 2.f*y + 1.f;
        float x2 = 2.f*x + 12.f, y2 = 2.f*y + 12.f;
        float q1 = fmaf(r0, 11.f, x1);
        float q2 = fmaf(r1, 11.f, y1);
        float q3 = fmaf(r2, 11.f, x2);
        float q4 = fmaf(r3, 11.f, y2);
        float rw = q3 - q1, rh = q4 - q2;
        float l = fmaxf(rw, rh);
        float nx1 = q1 + rw*0.5f - l*0.5f;
        float ny1 = q2 + rh*0.5f - l*0.5f;
        float* o = out + ((size_t)bb*KPICKS + tid)*5;
        o[0] = nx1; o[1] = ny1; o[2] = nx1 + l; o[3] = ny1 + l;
        o[4] = s_psc[tid];
    }
}

// ============================================================
extern "C" void kernel_launch(void* const* d_in, const int* in_sizes, int n_in,
                              void* d_out, int out_size)
{
    const float* im   = (const float*)d_in[0];
    const float* c1w  = (const float*)d_in[1];
    const float* c1b  = (const float*)d_in[2];
    const float* p1   = (const float*)d_in[3];
    const float* c2w  = (const float*)d_in[4];
    const float* c2b  = (const float*)d_in[5];
    const float* p2   = (const float*)d_in[6];
    const float* c3w  = (const float*)d_in[7];
    const float* c3b  = (const float*)d_in[8];
    const float* p3   = (const float*)d_in[9];
    const float* c41w = (const float*)d_in[10];
    const float* c41b = (const float*)d_in[11];
    const float* c42w = (const float*)d_in[12];
    const float* c42b = (const float*)d_in[13];
    float* out = (float*)d_out;

    // stage packed weights; ONE copy into the single constant bank
    k0_pack<<<1, 256>>>(c1w, c2w, c3w);
    void* stage_ptr = nullptr;
    cudaGetSymbolAddress(&stage_ptr, g_stage);
    cudaMemcpyToSymbolAsync(c_wall, stage_ptr, (size_t)WTOT*8, 0,
                            cudaMemcpyDeviceToDevice, 0);

    dim3 blk1(32, 8, 1);
    dim3 g1(8, 24, BB);

    dim3 blk2(32, 4, 1);
    dim3 g2(2, 48, BB);   // 48*4 rows cover 189 (pad rows early-out)
    dim3 g3(2, 47, BB);   // 47*4 rows cover 187 (pad row early-out)

    k1_conv1_pool<<<g1, blk1>>>(im, c1b, p1);
    k2_conv2<<<g2, blk2>>>(c2b, p2);
    k3_conv3_heads<<<g3, blk2>>>(c3b, p3, c41w, c41b);
    k4_nms<<<BB, 256>>>(c3b, p3, c42w, c42b, out);
}